// round 1
// baseline (speedup 1.0000x reference)
#include <cuda_runtime.h>

#define NRAYS_MAX 8192
#define S 128
#define H 64

// One block per ray, one thread per sample.
__global__ __launch_bounds__(128, 4)
void render_kernel(const float* __restrict__ rays_o,
                   const float* __restrict__ rays_d,
                   const float* __restrict__ nearv,
                   const float* __restrict__ farv,
                   const float* __restrict__ jitter,
                   const float* __restrict__ density,
                   const float* __restrict__ W1,
                   const float* __restrict__ b1,
                   const float* __restrict__ W2,
                   const float* __restrict__ b2,
                   const float* __restrict__ Wsig,
                   const float* __restrict__ bsig,
                   const float* __restrict__ Wrgb,
                   const float* __restrict__ brgb,
                   float* __restrict__ out)
{
    __shared__ float sW2[H * H];     // row-major [i][j], rows float4-aligned
    __shared__ float sW1[3 * H];
    __shared__ float sb1[H];
    __shared__ float sb2[H];
    __shared__ float sWsig[H];
    __shared__ float sWrgb[3 * H];   // transposed: sWrgb[c*H + j] = Wrgb[j*3 + c]
    __shared__ float sF[S];          // cumprod scan buffer
    __shared__ float sA[S];          // alpha
    __shared__ float sR[S], sG[S], sB[S];

    const int t   = threadIdx.x;     // sample index 0..127
    const int ray = blockIdx.x;

    // ---- stage weights into shared ----
    for (int i = t; i < H * H; i += 128) sW2[i] = W2[i];
    for (int i = t; i < 3 * H; i += 128) sW1[i] = W1[i];
    for (int i = t; i < 3 * H; i += 128) {
        int j = i % H, c = i / H;
        sWrgb[c * H + j] = Wrgb[j * 3 + c];
    }
    if (t < H) { sb1[t] = b1[t]; sb2[t] = b2[t]; sWsig[t] = Wsig[t]; }
    __syncthreads();

    const float ox = rays_o[ray * 3 + 0];
    const float oy = rays_o[ray * 3 + 1];
    const float oz = rays_o[ray * 3 + 2];
    const float dx = rays_d[ray * 3 + 0];
    const float dy = rays_d[ray * 3 + 1];
    const float dz = rays_d[ray * 3 + 2];
    const float nr = nearv[ray];
    const float fr = farv[ray];
    const float step = (fr - nr) * (1.0f / (float)S);
    const float z = nr + (float)t * step;

    // ---- occupancy-grid test at the un-jittered point (matches reference order) ----
    const float p0x = ox + z * dx;
    const float p0y = oy + z * dy;
    const float p0z = oz + z * dz;
    const float ux = (p0x - (-1.25f)) / 2.5f;
    const float uy = (p0y - (-1.55f)) / 2.5f;
    const float uz = (p0z - (-1.25f)) / 2.5f;
    const int ix = (int)floorf(ux * 64.0f);
    const int iy = (int)floorf(uy * 64.0f);
    const int iz = (int)floorf(uz * 64.0f);
    const bool inb = (ix >= 0) & (ix < 64) & (iy >= 0) & (iy < 64) & (iz >= 0) & (iz < 64);
    const int cx = min(max(ix, 0), 63);
    const int cy = min(max(iy, 0), 63);
    const int cz = min(max(iz, 0), 63);
    const bool occ = density[(cx * 64 + cy) * 64 + cz] > 0.5f;
    const bool mask = occ && inb;    // z > 0 always (near >= 0.05)

    const float zv = mask ? z : 0.0f;
    const float zj = zv + jitter[ray * S + t] * step;

    float alpha = 0.0f, r = 0.0f, g = 0.0f, b = 0.0f;

    if (mask) {
        const float px = ox + zj * dx;
        const float py = oy + zj * dy;
        const float pz = oz + zj * dz;

        // ---- layer 1: h1 = relu(pts @ W1 + b1) ----
        float h1v[H];
        #pragma unroll
        for (int j = 0; j < H; j++) {
            float v = sb1[j];
            v = fmaf(px, sW1[j], v);
            v = fmaf(py, sW1[H + j], v);
            v = fmaf(pz, sW1[2 * H + j], v);
            h1v[j] = fmaxf(v, 0.0f);
        }

        // ---- layer 2 + heads, fused over 4 blocks of 16 outputs ----
        float sigma = bsig[0];
        float cr = brgb[0], cg = brgb[1], cb = brgb[2];

        #pragma unroll
        for (int jb = 0; jb < H; jb += 16) {
            float acc[16];
            #pragma unroll
            for (int k = 0; k < 16; k++) acc[k] = sb2[jb + k];

            #pragma unroll
            for (int i = 0; i < H; i++) {
                const float hi = h1v[i];
                const float4* wp = reinterpret_cast<const float4*>(sW2 + i * H + jb);
                const float4 w0 = wp[0];
                const float4 w1 = wp[1];
                const float4 w2v = wp[2];
                const float4 w3 = wp[3];
                acc[0]  = fmaf(hi, w0.x,  acc[0]);
                acc[1]  = fmaf(hi, w0.y,  acc[1]);
                acc[2]  = fmaf(hi, w0.z,  acc[2]);
                acc[3]  = fmaf(hi, w0.w,  acc[3]);
                acc[4]  = fmaf(hi, w1.x,  acc[4]);
                acc[5]  = fmaf(hi, w1.y,  acc[5]);
                acc[6]  = fmaf(hi, w1.z,  acc[6]);
                acc[7]  = fmaf(hi, w1.w,  acc[7]);
                acc[8]  = fmaf(hi, w2v.x, acc[8]);
                acc[9]  = fmaf(hi, w2v.y, acc[9]);
                acc[10] = fmaf(hi, w2v.z, acc[10]);
                acc[11] = fmaf(hi, w2v.w, acc[11]);
                acc[12] = fmaf(hi, w3.x,  acc[12]);
                acc[13] = fmaf(hi, w3.y,  acc[13]);
                acc[14] = fmaf(hi, w3.z,  acc[14]);
                acc[15] = fmaf(hi, w3.w,  acc[15]);
            }

            #pragma unroll
            for (int k = 0; k < 16; k++) {
                const float h2 = fmaxf(acc[k], 0.0f);
                sigma = fmaf(h2, sWsig[jb + k], sigma);
                cr = fmaf(h2, sWrgb[jb + k], cr);
                cg = fmaf(h2, sWrgb[H + jb + k], cg);
                cb = fmaf(h2, sWrgb[2 * H + jb + k], cb);
            }
        }

        const float tau = fmaxf(sigma, 0.0f) * step;
        alpha = 1.0f - __expf(-tau);
        r = 1.0f / (1.0f + __expf(-cr));
        g = 1.0f / (1.0f + __expf(-cg));
        b = 1.0f / (1.0f + __expf(-cb));
    }

    // ---- composite: inclusive product scan of (1 - alpha + 1e-10) ----
    sA[t] = alpha;
    sF[t] = 1.0f - alpha + 1e-10f;
    sR[t] = r; sG[t] = g; sB[t] = b;
    __syncthreads();

    #pragma unroll
    for (int off = 1; off < S; off <<= 1) {
        const float v = sF[t];
        const float m = (t >= off) ? sF[t - off] : 1.0f;
        __syncthreads();
        sF[t] = v * m;
        __syncthreads();
    }

    const float excl = (t == 0) ? 1.0f : sF[t - 1];   // transmittance before sample t
    const float w = sA[t] * excl;
    const float wr = w * sR[t];
    const float wg = w * sG[t];
    const float wb = w * sB[t];
    __syncthreads();
    sR[t] = wr; sG[t] = wg; sB[t] = wb;
    __syncthreads();

    #pragma unroll
    for (int off = 64; off > 0; off >>= 1) {
        if (t < off) {
            sR[t] += sR[t + off];
            sG[t] += sG[t + off];
            sB[t] += sB[t + off];
        }
        __syncthreads();
    }

    if (t == 0) {
        const float no_hit = sF[S - 1];   // full transmittance -> white background
        out[ray * 3 + 0] = sR[0] + no_hit;
        out[ray * 3 + 1] = sG[0] + no_hit;
        out[ray * 3 + 2] = sB[0] + no_hit;
    }
}

extern "C" void kernel_launch(void* const* d_in, const int* in_sizes, int n_in,
                              void* d_out, int out_size)
{
    const float* rays_o  = (const float*)d_in[0];
    const float* rays_d  = (const float*)d_in[1];
    const float* nearv   = (const float*)d_in[2];
    const float* farv    = (const float*)d_in[3];
    const float* jitter  = (const float*)d_in[4];
    const float* density = (const float*)d_in[5];
    const float* W1      = (const float*)d_in[6];
    const float* b1      = (const float*)d_in[7];
    const float* W2      = (const float*)d_in[8];
    const float* b2      = (const float*)d_in[9];
    const float* Wsig    = (const float*)d_in[10];
    const float* bsig    = (const float*)d_in[11];
    const float* Wrgb    = (const float*)d_in[12];
    const float* brgb    = (const float*)d_in[13];

    const int n_rays = in_sizes[2];   // near has one entry per ray

    render_kernel<<<n_rays, 128>>>(rays_o, rays_d, nearv, farv, jitter, density,
                                   W1, b1, W2, b2, Wsig, bsig, Wrgb, brgb,
                                   (float*)d_out);
}

// round 5
// speedup vs baseline: 2.3662x; 2.3662x over previous
#include <cuda_runtime.h>
#include <cuda_fp16.h>
#include <mma.h>

using namespace nvcuda;

#define S 128
#define H 64
#define LDH 72   // padded leading dim (elements); same for half h1 and float h2

// Dynamic shared memory layout (bytes):
//   [0, 36864)      aliased: { h1_hi half[128*72] @0 ; h1_lo half[128*72] @18432 }
//                   later:   h2 float[128*72] (exact overlap)
//   [36864, 46080)  W2_hi half[64*72]
//   [46080, 55296)  W2_lo half[64*72]
//   [55296, 56064)  sW1  float[3*64]
//   [56064, 56320)  sb1  float[64]
//   [56320, 56576)  sb2  float[64]
//   [56576, 56832)  sWsig float[64]
//   [56832, 57600)  sWrgb float[3*64] (transposed [c][j])
//   [57600, 57616)  sWprod float[4]
//   [57616, 57664)  sSum float[4][3]
#define SMEM_BYTES 57664

__global__ __launch_bounds__(128, 4)
void render_kernel(const float* __restrict__ rays_o,
                   const float* __restrict__ rays_d,
                   const float* __restrict__ nearv,
                   const float* __restrict__ farv,
                   const float* __restrict__ jitter,
                   const float* __restrict__ density,
                   const float* __restrict__ W1,
                   const float* __restrict__ b1,
                   const float* __restrict__ W2,
                   const float* __restrict__ b2,
                   const float* __restrict__ Wsig,
                   const float* __restrict__ bsig,
                   const float* __restrict__ Wrgb,
                   const float* __restrict__ brgb,
                   float* __restrict__ out)
{
    extern __shared__ __align__(16) char smem[];
    __half* hH1hi = reinterpret_cast<__half*>(smem);
    __half* hH1lo = reinterpret_cast<__half*>(smem + 18432);
    float*  fH2   = reinterpret_cast<float*>(smem);            // aliases h1 pair
    __half* sW2hi = reinterpret_cast<__half*>(smem + 36864);
    __half* sW2lo = reinterpret_cast<__half*>(smem + 46080);
    float*  sW1   = reinterpret_cast<float*>(smem + 55296);
    float*  sb1   = reinterpret_cast<float*>(smem + 56064);
    float*  sb2   = reinterpret_cast<float*>(smem + 56320);
    float*  sWsig = reinterpret_cast<float*>(smem + 56576);
    float*  sWrgb = reinterpret_cast<float*>(smem + 56832);
    float*  sWprod = reinterpret_cast<float*>(smem + 57600);
    float*  sSum   = reinterpret_cast<float*>(smem + 57616);   // [4][3]

    const int t    = threadIdx.x;
    const int lane = t & 31;
    const int warp = t >> 5;
    const int ray  = blockIdx.x;

    // ---- per-sample ray setup + occupancy-grid mask ----
    const float ox = rays_o[ray * 3 + 0];
    const float oy = rays_o[ray * 3 + 1];
    const float oz = rays_o[ray * 3 + 2];
    const float dx = rays_d[ray * 3 + 0];
    const float dy = rays_d[ray * 3 + 1];
    const float dz = rays_d[ray * 3 + 2];
    const float nr = nearv[ray];
    const float fr = farv[ray];
    const float step = (fr - nr) * (1.0f / (float)S);
    const float z = nr + (float)t * step;

    const float p0x = ox + z * dx;
    const float p0y = oy + z * dy;
    const float p0z = oz + z * dz;
    const float ux = (p0x - (-1.25f)) / 2.5f;
    const float uy = (p0y - (-1.55f)) / 2.5f;
    const float uz = (p0z - (-1.25f)) / 2.5f;
    const int ix = (int)floorf(ux * 64.0f);
    const int iy = (int)floorf(uy * 64.0f);
    const int iz = (int)floorf(uz * 64.0f);
    const bool inb = (ix >= 0) & (ix < 64) & (iy >= 0) & (iy < 64) & (iz >= 0) & (iz < 64);
    const int cx = min(max(ix, 0), 63);
    const int cy = min(max(iy, 0), 63);
    const int cz = min(max(iz, 0), 63);
    const bool occ = density[(cx * 64 + cy) * 64 + cz] > 0.5f;
    const bool mask = occ && inb;

    // Whole-ray empty? -> exact white (1 - 0 + 1e-10 rounds to 1.0f).
    const int any_active = __syncthreads_or(mask ? 1 : 0);
    if (!any_active) {
        if (t == 0) {
            out[ray * 3 + 0] = 1.0f;
            out[ray * 3 + 1] = 1.0f;
            out[ray * 3 + 2] = 1.0f;
        }
        return;
    }

    const float zv = mask ? z : 0.0f;
    const float zj = zv + jitter[ray * S + t] * step;
    const float px = ox + zj * dx;
    const float py = oy + zj * dy;
    const float pz = oz + zj * dz;

    // ---- stage weights (W2 split into hi + lo fp16) ----
    for (int i = t; i < H * H; i += 128) {
        const int k = i >> 6, j = i & 63;
        const float w = W2[i];
        const __half whi = __float2half_rn(w);
        const __half wlo = __float2half_rn(w - __half2float(whi));
        sW2hi[k * LDH + j] = whi;
        sW2lo[k * LDH + j] = wlo;
    }
    for (int i = t; i < 3 * H; i += 128) sW1[i] = W1[i];
    for (int i = t; i < 3 * H; i += 128) {
        const int j = i % H, c = i / H;
        sWrgb[c * H + j] = Wrgb[j * 3 + c];
    }
    if (t < H) { sb1[t] = b1[t]; sb2[t] = b2[t]; sWsig[t] = Wsig[t]; }

    // All staged shared data must be visible before ANY thread reads it.
    // (This barrier was missing in rounds 2-4: layer 1 read sW1/sb1 entries
    //  written by other warps -> read-before-write race -> ~3e-3 "noise".)
    __syncthreads();

    // ---- layer 1 (scalar fp32, K=3): h1 split into hi + lo fp16 rows ----
    {
        __half* hrowHi = hH1hi + t * LDH;
        __half* hrowLo = hH1lo + t * LDH;
        #pragma unroll
        for (int j = 0; j < H; j++) {
            float v = sb1[j];
            v = fmaf(px, sW1[j], v);
            v = fmaf(py, sW1[H + j], v);
            v = fmaf(pz, sW1[2 * H + j], v);
            v = fmaxf(v, 0.0f);
            const __half vhi = __float2half_rn(v);
            const __half vlo = __float2half_rn(v - __half2float(vhi));
            hrowHi[j] = vhi;
            hrowLo[j] = vlo;
        }
    }
    __syncthreads();

    // ---- layer 2: [128x64] = h1[128x64] x W2[64x64], split fp16 (Markidis) ----
    // h2 = h_hi*w_hi + h_hi*w_lo + h_lo*w_hi (fp32 accum); lo*lo term ~2^-22, dropped.
    wmma::fragment<wmma::accumulator, 16, 16, 16, float> c[2][4];
    #pragma unroll
    for (int mt = 0; mt < 2; mt++)
        #pragma unroll
        for (int nt = 0; nt < 4; nt++)
            wmma::fill_fragment(c[mt][nt], 0.0f);

    #pragma unroll
    for (int k = 0; k < 4; k++) {
        wmma::fragment<wmma::matrix_a, 16, 16, 16, __half, wmma::row_major> aHi0, aHi1, aLo0, aLo1;
        wmma::load_matrix_sync(aHi0, hH1hi + (warp * 32) * LDH + k * 16, LDH);
        wmma::load_matrix_sync(aHi1, hH1hi + (warp * 32 + 16) * LDH + k * 16, LDH);
        wmma::load_matrix_sync(aLo0, hH1lo + (warp * 32) * LDH + k * 16, LDH);
        wmma::load_matrix_sync(aLo1, hH1lo + (warp * 32 + 16) * LDH + k * 16, LDH);
        #pragma unroll
        for (int nt = 0; nt < 4; nt++) {
            wmma::fragment<wmma::matrix_b, 16, 16, 16, __half, wmma::row_major> bHi, bLo;
            wmma::load_matrix_sync(bHi, sW2hi + (k * 16) * LDH + nt * 16, LDH);
            wmma::load_matrix_sync(bLo, sW2lo + (k * 16) * LDH + nt * 16, LDH);
            wmma::mma_sync(c[0][nt], aHi0, bHi, c[0][nt]);
            wmma::mma_sync(c[1][nt], aHi1, bHi, c[1][nt]);
            wmma::mma_sync(c[0][nt], aHi0, bLo, c[0][nt]);
            wmma::mma_sync(c[1][nt], aHi1, bLo, c[1][nt]);
            wmma::mma_sync(c[0][nt], aLo0, bHi, c[0][nt]);
            wmma::mma_sync(c[1][nt], aLo1, bHi, c[1][nt]);
        }
    }

    // fH2 aliases the h1 buffers: all MMA reads must complete before stores.
    __syncthreads();
    #pragma unroll
    for (int mt = 0; mt < 2; mt++)
        #pragma unroll
        for (int nt = 0; nt < 4; nt++)
            wmma::store_matrix_sync(fH2 + (warp * 32 + mt * 16) * LDH + nt * 16,
                                    c[mt][nt], LDH, wmma::mem_row_major);
    __syncthreads();

    // ---- heads (scalar fp32), only for active samples ----
    float alpha = 0.0f, r = 0.0f, g = 0.0f, b = 0.0f;
    if (mask) {
        float sigma = bsig[0];
        float cr = brgb[0], cg = brgb[1], cb = brgb[2];
        const float4* hrow = reinterpret_cast<const float4*>(fH2 + t * LDH);
        #pragma unroll
        for (int jq = 0; jq < 16; jq++) {
            const float4 hv = hrow[jq];
            const int j = jq * 4;
            const float h0 = fmaxf(hv.x + sb2[j + 0], 0.0f);
            const float h1 = fmaxf(hv.y + sb2[j + 1], 0.0f);
            const float h2 = fmaxf(hv.z + sb2[j + 2], 0.0f);
            const float h3 = fmaxf(hv.w + sb2[j + 3], 0.0f);
            sigma = fmaf(h0, sWsig[j + 0], sigma);
            sigma = fmaf(h1, sWsig[j + 1], sigma);
            sigma = fmaf(h2, sWsig[j + 2], sigma);
            sigma = fmaf(h3, sWsig[j + 3], sigma);
            cr = fmaf(h0, sWrgb[j + 0], cr);
            cr = fmaf(h1, sWrgb[j + 1], cr);
            cr = fmaf(h2, sWrgb[j + 2], cr);
            cr = fmaf(h3, sWrgb[j + 3], cr);
            cg = fmaf(h0, sWrgb[H + j + 0], cg);
            cg = fmaf(h1, sWrgb[H + j + 1], cg);
            cg = fmaf(h2, sWrgb[H + j + 2], cg);
            cg = fmaf(h3, sWrgb[H + j + 3], cg);
            cb = fmaf(h0, sWrgb[2 * H + j + 0], cb);
            cb = fmaf(h1, sWrgb[2 * H + j + 1], cb);
            cb = fmaf(h2, sWrgb[2 * H + j + 2], cb);
            cb = fmaf(h3, sWrgb[2 * H + j + 3], cb);
        }
        const float tau = fmaxf(sigma, 0.0f) * step;
        alpha = 1.0f - __expf(-tau);
        r = 1.0f / (1.0f + __expf(-cr));
        g = 1.0f / (1.0f + __expf(-cg));
        b = 1.0f / (1.0f + __expf(-cb));
    }

    // ---- composite: warp-shuffle scan + cross-warp combine ----
    const float f = 1.0f - alpha + 1e-10f;
    float incl = f;
    #pragma unroll
    for (int off = 1; off < 32; off <<= 1) {
        const float v = __shfl_up_sync(0xffffffffu, incl, off);
        if (lane >= off) incl *= v;
    }
    const float wtot = __shfl_sync(0xffffffffu, incl, 31);
    if (lane == 0) sWprod[warp] = wtot;
    __syncthreads();

    float pre = 1.0f;
    #pragma unroll
    for (int i = 0; i < 4; i++) if (i < warp) pre *= sWprod[i];

    float excl = __shfl_up_sync(0xffffffffu, incl, 1);
    if (lane == 0) excl = 1.0f;

    const float w = alpha * pre * excl;
    float wr = w * r, wg = w * g, wb = w * b;
    #pragma unroll
    for (int off = 16; off > 0; off >>= 1) {
        wr += __shfl_down_sync(0xffffffffu, wr, off);
        wg += __shfl_down_sync(0xffffffffu, wg, off);
        wb += __shfl_down_sync(0xffffffffu, wb, off);
    }
    if (lane == 0) { sSum[warp * 3 + 0] = wr; sSum[warp * 3 + 1] = wg; sSum[warp * 3 + 2] = wb; }
    __syncthreads();

    if (t == 0) {
        const float no_hit = sWprod[0] * sWprod[1] * sWprod[2] * sWprod[3];
        float c0 = no_hit, c1 = no_hit, c2 = no_hit;
        #pragma unroll
        for (int i = 0; i < 4; i++) {
            c0 += sSum[i * 3 + 0];
            c1 += sSum[i * 3 + 1];
            c2 += sSum[i * 3 + 2];
        }
        out[ray * 3 + 0] = c0;
        out[ray * 3 + 1] = c1;
        out[ray * 3 + 2] = c2;
    }
}

extern "C" void kernel_launch(void* const* d_in, const int* in_sizes, int n_in,
                              void* d_out, int out_size)
{
    const float* rays_o  = (const float*)d_in[0];
    const float* rays_d  = (const float*)d_in[1];
    const float* nearv   = (const float*)d_in[2];
    const float* farv    = (const float*)d_in[3];
    const float* jitter  = (const float*)d_in[4];
    const float* density = (const float*)d_in[5];
    const float* W1      = (const float*)d_in[6];
    const float* b1      = (const float*)d_in[7];
    const float* W2      = (const float*)d_in[8];
    const float* b2      = (const float*)d_in[9];
    const float* Wsig    = (const float*)d_in[10];
    const float* bsig    = (const float*)d_in[11];
    const float* Wrgb    = (const float*)d_in[12];
    const float* brgb    = (const float*)d_in[13];

    const int n_rays = in_sizes[2];   // near has one entry per ray

    cudaFuncSetAttribute(render_kernel, cudaFuncAttributeMaxDynamicSharedMemorySize, SMEM_BYTES);

    render_kernel<<<n_rays, 128, SMEM_BYTES>>>(rays_o, rays_d, nearv, farv, jitter, density,
                                               W1, b1, W2, b2, Wsig, bsig, Wrgb, brgb,
                                               (float*)d_out);
}